// round 2
// baseline (speedup 1.0000x reference)
#include <cuda_runtime.h>

#define NB 16
#define HWPIX (768*768)          // 589824 pixels per batch
#define NUM_IDS 128
#define NVEC (HWPIX/4)           // 147456 int4/float4 per batch-plane
#define FXS 8192.0f              // 2^13 fixed-point scale
#define FXI (1.0f/8192.0f)

typedef unsigned long long ull;

// ---- scratch (allocation-free: __device__ globals) ----
__device__ int   g_cnt [NB * NUM_IDS];
__device__ float g_fsin[NB * NUM_IDS];
__device__ float g_fcos[NB * NUM_IDS];

// ---------------------------------------------------------------------------
// K0: zero scratch (every launch, so graph replays are deterministic)
// ---------------------------------------------------------------------------
__global__ void k_zero() {
    int i = blockIdx.x * blockDim.x + threadIdx.x;
    if (i < NB * NUM_IDS) {
        g_cnt[i]  = 0;
        g_fsin[i] = 0.0f;
        g_fcos[i] = 0.0f;
    }
}

// ---------------------------------------------------------------------------
// K1: single fused streaming pass.
// Per pixel: count histogram + per-id partial sums of |psin-gsin|, |pcos-gcos|.
// S_sin/S_cos packed as 2^13 fixed-point halves of ONE 64-bit shared atomic
// (2 shared atomics per pixel total). Block tables flushed to global floats.
// grid = (37, NB) = 592 blocks = 4 per SM; block = 256.
// ---------------------------------------------------------------------------
__global__ void __launch_bounds__(256) k_main(const float* __restrict__ pred,
                                              const int*   __restrict__ inst,
                                              const float* __restrict__ gt) {
    const int b = blockIdx.y;
    __shared__ ull s_sc [NUM_IDS];   // low32 = sin fx-sum, high32 = cos fx-sum
    __shared__ int s_cnt[NUM_IDS];
    for (int i = threadIdx.x; i < NUM_IDS; i += blockDim.x) {
        s_sc[i] = 0ULL; s_cnt[i] = 0;
    }
    __syncthreads();

    const float4* ps = (const float4*)(pred + (size_t)b * 2 * HWPIX);
    const float4* pc = (const float4*)(pred + (size_t)b * 2 * HWPIX + HWPIX);
    const float4* gs = (const float4*)(gt   + (size_t)b * 5 * HWPIX + 2 * (size_t)HWPIX);
    const float4* gc = (const float4*)(gt   + (size_t)b * 5 * HWPIX + 3 * (size_t)HWPIX);
    const int4*   pi = (const int4*)(inst + (size_t)b * HWPIX);

    for (int i = blockIdx.x * blockDim.x + threadIdx.x; i < NVEC;
         i += gridDim.x * blockDim.x) {
        int4   id = pi[i];
        float4 s  = ps[i];
        float4 c  = pc[i];
        float4 g1 = gs[i];
        float4 g2 = gc[i];

        unsigned sn0 = __float2uint_rn(fabsf(s.x - g1.x) * FXS);
        unsigned sn1 = __float2uint_rn(fabsf(s.y - g1.y) * FXS);
        unsigned sn2 = __float2uint_rn(fabsf(s.z - g1.z) * FXS);
        unsigned sn3 = __float2uint_rn(fabsf(s.w - g1.w) * FXS);
        unsigned cs0 = __float2uint_rn(fabsf(c.x - g2.x) * FXS);
        unsigned cs1 = __float2uint_rn(fabsf(c.y - g2.y) * FXS);
        unsigned cs2 = __float2uint_rn(fabsf(c.z - g2.z) * FXS);
        unsigned cs3 = __float2uint_rn(fabsf(c.w - g2.w) * FXS);

        atomicAdd(&s_sc[id.x], ((ull)cs0 << 32) | (ull)sn0);
        atomicAdd(&s_sc[id.y], ((ull)cs1 << 32) | (ull)sn1);
        atomicAdd(&s_sc[id.z], ((ull)cs2 << 32) | (ull)sn2);
        atomicAdd(&s_sc[id.w], ((ull)cs3 << 32) | (ull)sn3);
        atomicAdd(&s_cnt[id.x], 1);
        atomicAdd(&s_cnt[id.y], 1);
        atomicAdd(&s_cnt[id.z], 1);
        atomicAdd(&s_cnt[id.w], 1);
    }
    __syncthreads();

    // flush: unpack fixed-point -> float BEFORE global accumulation
    // (avoids cross-block fixed-point overflow)
    for (int i = threadIdx.x; i < NUM_IDS; i += blockDim.x) {
        int cn = s_cnt[i];
        if (cn) {
            ull v = s_sc[i];
            atomicAdd(&g_cnt [b * NUM_IDS + i], cn);
            atomicAdd(&g_fsin[b * NUM_IDS + i], (float)(unsigned)(v)        * FXI);
            atomicAdd(&g_fcos[b * NUM_IDS + i], (float)(unsigned)(v >> 32)  * FXI);
        }
    }
}

// ---------------------------------------------------------------------------
// K2: finalize. One block, 512 threads = 16 warps.
// Phase 1: block-reduce num_instances (global) and num_bg_pixels (global).
// Phase 2: warp w owns batch w: dot(S, inv_norm) over 128 ids -> output tuple.
// ---------------------------------------------------------------------------
__global__ void __launch_bounds__(512) k_fin(float* __restrict__ out) {
    const int tid = threadIdx.x;
    __shared__ int sni[512], snbg[512];

    int ni = 0, nbg = 0;
    for (int i = tid; i < NB * NUM_IDS; i += 512) {
        int c  = g_cnt[i];
        int id = i & (NUM_IDS - 1);
        if (id == 0) nbg += c;
        else         ni  += (c > 0);
    }
    sni[tid] = ni; snbg[tid] = nbg;
    __syncthreads();
    for (int s = 256; s > 0; s >>= 1) {
        if (tid < s) { sni[tid] += sni[tid + s]; snbg[tid] += snbg[tid + s]; }
        __syncthreads();
    }
    __shared__ float inv_bg, two_ni;
    if (tid == 0) {
        inv_bg = 1.0f / (2.0f * (float)snbg[0]);
        two_ni = 2.0f * (float)sni[0];
    }
    __syncthreads();

    const int w = tid >> 5, lane = tid & 31;   // warp w = batch w
    float asin_ = 0.0f, acos_ = 0.0f;
    for (int l = lane; l < NUM_IDS; l += 32) {
        int   idx = w * NUM_IDS + l;
        int   cnt = g_cnt[idx];
        float inv = (l == 0) ? inv_bg
                             : ((cnt > 0) ? 1.0f / ((float)cnt * two_ni) : 0.0f);
        asin_ += g_fsin[idx] * inv;
        acos_ += g_fcos[idx] * inv;
    }
    for (int off = 16; off > 0; off >>= 1) {
        asin_ += __shfl_down_sync(0xFFFFFFFFu, asin_, off);
        acos_ += __shfl_down_sync(0xFFFFFFFFu, acos_, off);
    }
    if (lane == 0) {
        float t = asin_ + acos_;
        out[0 * NB + w] = t;       // loss
        out[1 * NB + w] = t;       // loss_direction_total
        out[2 * NB + w] = 0.0f;    // loss_centers
        out[3 * NB + w] = asin_;   // loss_sin
        out[4 * NB + w] = acos_;   // loss_cos
    }
}

extern "C" void kernel_launch(void* const* d_in, const int* in_sizes, int n_in,
                              void* d_out, int out_size) {
    const float* pred = (const float*)d_in[0];   // (16,2,768,768) f32
    const int*   inst = (const int*)d_in[1];     // (16,768,768) i32
    // d_in[2] = labels (unused: W_FG == W_BG == 1)
    const float* gt   = (const float*)d_in[3];   // (16,5,768,768) f32
    float* out = (float*)d_out;                  // 80 f32

    k_zero<<<8, 256>>>();
    k_main<<<dim3(37, NB), 256>>>(pred, inst, gt);
    k_fin<<<1, 512>>>(out);
}

// round 3
// speedup vs baseline: 1.0198x; 1.0198x over previous
#include <cuda_runtime.h>

#define NB 16
#define G 37                      // blocks per batch
#define NBLK (G * NB)             // 592 == 148 SMs * 4 blocks
#define HWPIX (768*768)
#define NUM_IDS 128
#define NVEC (HWPIX/4)

// ---- scratch (allocation-free). All data arrays are FULLY overwritten each
// run; the three counters are reset to 0 by the last block each run. ----
__device__ int   g_part [NBLK * NUM_IDS];   // per-block partial histograms
__device__ int   g_cnt  [NB * NUM_IDS];     // per-batch counts
__device__ int   g_ni   [NB];               // per-batch #instances
__device__ int   g_nbg  [NB];               // per-batch bg pixel count
__device__ float g_ploss[NBLK * 2];         // per-block partial (sin,cos)
__device__ int   g_bar0, g_bar1, g_tix;     // zero-init; self-resetting

__device__ __forceinline__ void grid_barrier(int* ctr) {
    __threadfence();
    __syncthreads();
    if (threadIdx.x == 0) {
        atomicAdd(ctr, 1);
        while (*(volatile int*)ctr < NBLK) { }
    }
    __syncthreads();
}

__global__ void __launch_bounds__(256, 4)
k_all(const float* __restrict__ pred,
      const int*   __restrict__ inst,
      const float* __restrict__ gt,
      float*       __restrict__ out) {
    const int tid  = threadIdx.x;
    const int b    = blockIdx.y;
    const int bx   = blockIdx.x;
    const int bid  = b * G + bx;

    __shared__ int   s_hist[NUM_IDS];
    __shared__ float s_inv [NUM_IDS];
    __shared__ int   s_red [256];

    // ---------------- Phase 1: per-block histogram of instance ids ----------
    for (int i = tid; i < NUM_IDS; i += 256) s_hist[i] = 0;
    __syncthreads();

    const int4* pi = (const int4*)(inst + (size_t)b * HWPIX);
    for (int i = bx * 256 + tid; i < NVEC; i += G * 256) {
        int4 v = pi[i];
        atomicAdd(&s_hist[v.x], 1);
        atomicAdd(&s_hist[v.y], 1);
        atomicAdd(&s_hist[v.z], 1);
        atomicAdd(&s_hist[v.w], 1);
    }
    __syncthreads();
    for (int i = tid; i < NUM_IDS; i += 256)
        g_part[bid * NUM_IDS + i] = s_hist[i];

    grid_barrier(&g_bar0);

    // ---------------- Phase 2: 16 blocks (bx==0) reduce partials ------------
    if (bx == 0) {
        int myni = 0;
        if (tid < NUM_IDS) {
            int tot = 0;
            #pragma unroll 1
            for (int x = 0; x < G; x++)
                tot += g_part[(b * G + x) * NUM_IDS + tid];
            g_cnt[b * NUM_IDS + tid] = tot;
            if (tid == 0) g_nbg[b] = tot;
            else          myni = (tot > 0);
        }
        s_red[tid] = myni;
        __syncthreads();
        for (int s = 128; s > 0; s >>= 1) {
            if (tid < s) s_red[tid] += s_red[tid + s];
            __syncthreads();
        }
        if (tid == 0) g_ni[b] = s_red[0];
    }

    grid_barrier(&g_bar1);

    // ---------------- Phase 3: weighted L1 stream ---------------------------
    float inv_bg, two_ni;
    {
        int ni = 0, nbg = 0;
        #pragma unroll
        for (int i = 0; i < NB; i++) { ni += g_ni[i]; nbg += g_nbg[i]; }
        inv_bg = 1.0f / (2.0f * (float)nbg);
        two_ni = 2.0f * (float)ni;
    }
    for (int i = tid; i < NUM_IDS; i += 256) {
        float c = (float)max(g_cnt[b * NUM_IDS + i], 1);
        s_inv[i] = (i == 0) ? inv_bg : 1.0f / (c * two_ni);
    }
    __syncthreads();

    const float4* ps = (const float4*)(pred + (size_t)b * 2 * HWPIX);
    const float4* pc = (const float4*)(pred + (size_t)b * 2 * HWPIX + HWPIX);
    const float4* gs = (const float4*)(gt   + (size_t)b * 5 * HWPIX + 2 * (size_t)HWPIX);
    const float4* gc = (const float4*)(gt   + (size_t)b * 5 * HWPIX + 3 * (size_t)HWPIX);

    float asin_ = 0.0f, acos_ = 0.0f;
    for (int i = bx * 256 + tid; i < NVEC; i += G * 256) {
        int4   id = pi[i];
        float4 s  = ps[i];
        float4 c  = pc[i];
        float4 g1 = gs[i];
        float4 g2 = gc[i];
        float w0 = s_inv[id.x], w1 = s_inv[id.y], w2 = s_inv[id.z], w3 = s_inv[id.w];
        asin_ += w0 * fabsf(s.x - g1.x) + w1 * fabsf(s.y - g1.y)
               + w2 * fabsf(s.z - g1.z) + w3 * fabsf(s.w - g1.w);
        acos_ += w0 * fabsf(c.x - g2.x) + w1 * fabsf(c.y - g2.y)
               + w2 * fabsf(c.z - g2.z) + w3 * fabsf(c.w - g2.w);
    }

    // block reduce (sin, cos)
    for (int off = 16; off > 0; off >>= 1) {
        asin_ += __shfl_down_sync(0xFFFFFFFFu, asin_, off);
        acos_ += __shfl_down_sync(0xFFFFFFFFu, acos_, off);
    }
    __shared__ float ws[8], wc[8];
    int lane = tid & 31, warp = tid >> 5;
    if (lane == 0) { ws[warp] = asin_; wc[warp] = acos_; }
    __syncthreads();
    if (tid == 0) {
        float vs = 0.0f, vc = 0.0f;
        #pragma unroll
        for (int i = 0; i < 8; i++) { vs += ws[i]; vc += wc[i]; }
        g_ploss[bid * 2 + 0] = vs;
        g_ploss[bid * 2 + 1] = vc;
    }

    // ---------------- Finale: last block reduces & writes output ------------
    __shared__ int s_last;
    if (tid == 0) {
        __threadfence();
        int t = atomicAdd(&g_tix, 1);
        s_last = (t == NBLK - 1);
    }
    __syncthreads();
    if (s_last) {
        __threadfence();
        // warp w handles batches w and w+8
        for (int bb = warp; bb < NB; bb += 8) {
            float ss = 0.0f, cc = 0.0f;
            for (int x = lane; x < G; x += 32) {
                ss += g_ploss[(bb * G + x) * 2 + 0];
                cc += g_ploss[(bb * G + x) * 2 + 1];
            }
            for (int off = 16; off > 0; off >>= 1) {
                ss += __shfl_down_sync(0xFFFFFFFFu, ss, off);
                cc += __shfl_down_sync(0xFFFFFFFFu, cc, off);
            }
            if (lane == 0) {
                float t2 = ss + cc;
                out[0 * NB + bb] = t2;     // loss
                out[1 * NB + bb] = t2;     // loss_direction_total
                out[2 * NB + bb] = 0.0f;   // loss_centers
                out[3 * NB + bb] = ss;     // loss_sin
                out[4 * NB + bb] = cc;     // loss_cos
            }
        }
        __syncthreads();
        if (tid == 0) { g_bar0 = 0; g_bar1 = 0; g_tix = 0; }
    }
}

extern "C" void kernel_launch(void* const* d_in, const int* in_sizes, int n_in,
                              void* d_out, int out_size) {
    const float* pred = (const float*)d_in[0];   // (16,2,768,768) f32
    const int*   inst = (const int*)d_in[1];     // (16,768,768) i32
    // d_in[2] = labels (unused: W_FG == W_BG == 1)
    const float* gt   = (const float*)d_in[3];   // (16,5,768,768) f32
    float* out = (float*)d_out;                  // 80 f32

    k_all<<<dim3(G, NB), 256>>>(pred, inst, gt, out);
}

// round 4
// speedup vs baseline: 1.0373x; 1.0172x over previous
#include <cuda_runtime.h>

#define NB 16
#define GH 37                     // hist blocks per batch
#define GL 48                     // loss blocks per batch
#define NLBLK (GL * NB)           // 768
#define HWPIX (768*768)
#define NUM_IDS 128
#define NVEC (HWPIX/4)            // 147456

// ---- scratch (allocation-free __device__ globals). Data arrays are fully
// overwritten each run; tickets are reset by their final consumer. ----
__device__ unsigned char g_pack[(size_t)NB * HWPIX];  // ids packed to bytes
__device__ int   g_part [GH * NB * NUM_IDS];          // per-block partial hists
__device__ int   g_cnt  [NB * NUM_IDS];               // per-batch counts
__device__ int   g_ni   [NB];                         // per-batch #instances
__device__ int   g_nbg  [NB];                         // per-batch bg pixels
__device__ float g_ploss[NLBLK * 2];                  // per-block (sin,cos)
__device__ int   g_tixh [NB];                         // per-batch hist tickets
__device__ int   g_tixl;                              // global loss ticket

// ---------------------------------------------------------------------------
// K1: histogram + id byte-packing. grid (GH, NB), 256 threads.
// Last block per batch reduces the GH partials -> g_cnt / g_ni / g_nbg.
// ---------------------------------------------------------------------------
__global__ void __launch_bounds__(256) k_hist(const int* __restrict__ inst) {
    const int tid = threadIdx.x;
    const int b   = blockIdx.y;
    const int bx  = blockIdx.x;

    __shared__ int sh[NUM_IDS];
    for (int i = tid; i < NUM_IDS; i += 256) sh[i] = 0;
    __syncthreads();

    const int4* pi = (const int4*)(inst + (size_t)b * HWPIX);
    uchar4*     pk = (uchar4*)(g_pack + (size_t)b * HWPIX);
    for (int i = bx * 256 + tid; i < NVEC; i += GH * 256) {
        int4 v = pi[i];
        pk[i] = make_uchar4((unsigned char)v.x, (unsigned char)v.y,
                            (unsigned char)v.z, (unsigned char)v.w);
        atomicAdd(&sh[v.x], 1);
        atomicAdd(&sh[v.y], 1);
        atomicAdd(&sh[v.z], 1);
        atomicAdd(&sh[v.w], 1);
    }
    __syncthreads();
    for (int i = tid; i < NUM_IDS; i += 256)
        g_part[(b * GH + bx) * NUM_IDS + i] = sh[i];

    // per-batch ticket: last block of this batch reduces the partials
    __shared__ int s_last;
    if (tid == 0) {
        __threadfence();
        s_last = (atomicAdd(&g_tixh[b], 1) == GH - 1);
    }
    __syncthreads();
    if (!s_last) return;
    __threadfence();

    __shared__ int s_red[256];
    int myni = 0;
    if (tid < NUM_IDS) {
        int tot = 0;
        #pragma unroll 1
        for (int x = 0; x < GH; x++)
            tot += g_part[(b * GH + x) * NUM_IDS + tid];
        g_cnt[b * NUM_IDS + tid] = tot;
        if (tid == 0) g_nbg[b] = tot;
        else          myni = (tot > 0);
    }
    s_red[tid] = myni;
    __syncthreads();
    for (int s = 128; s > 0; s >>= 1) {
        if (tid < s) s_red[tid] += s_red[tid + s];
        __syncthreads();
    }
    if (tid == 0) {
        g_ni[b]   = s_red[0];
        g_tixh[b] = 0;            // self-reset for next graph replay
    }
}

// ---------------------------------------------------------------------------
// K2: weighted-L1 stream using packed byte ids. grid (GL, NB), 256 threads.
// Zero atomics in the hot loop. Global-ticket last block writes the output.
// ---------------------------------------------------------------------------
__global__ void __launch_bounds__(256) k_loss(const float* __restrict__ pred,
                                              const float* __restrict__ gt,
                                              float*       __restrict__ out) {
    const int tid = threadIdx.x;
    const int b   = blockIdx.y;
    const int bx  = blockIdx.x;
    const int bid = b * GL + bx;

    // build per-batch inverse-norm table
    __shared__ float s_inv[NUM_IDS];
    {
        int ni = 0, nbg = 0;
        #pragma unroll
        for (int i = 0; i < NB; i++) { ni += g_ni[i]; nbg += g_nbg[i]; }
        float inv_bg = 1.0f / (2.0f * (float)nbg);
        float two_ni = 2.0f * (float)ni;
        for (int i = tid; i < NUM_IDS; i += 256) {
            float c = (float)max(g_cnt[b * NUM_IDS + i], 1);
            s_inv[i] = (i == 0) ? inv_bg : 1.0f / (c * two_ni);
        }
    }
    __syncthreads();

    const float4*   ps  = (const float4*)(pred + (size_t)b * 2 * HWPIX);
    const float4*   pc  = (const float4*)(pred + (size_t)b * 2 * HWPIX + HWPIX);
    const float4*   gs  = (const float4*)(gt + (size_t)b * 5 * HWPIX + 2 * (size_t)HWPIX);
    const float4*   gc  = (const float4*)(gt + (size_t)b * 5 * HWPIX + 3 * (size_t)HWPIX);
    const unsigned* pid = (const unsigned*)(g_pack + (size_t)b * HWPIX);

    float asin_ = 0.0f, acos_ = 0.0f;
    #pragma unroll 2
    for (int i = bx * 256 + tid; i < NVEC; i += GL * 256) {
        unsigned w  = pid[i];
        float4   s  = ps[i];
        float4   c  = pc[i];
        float4   g1 = gs[i];
        float4   g2 = gc[i];
        float w0 = s_inv[w & 0xFF];
        float w1 = s_inv[(w >> 8)  & 0xFF];
        float w2 = s_inv[(w >> 16) & 0xFF];
        float w3 = s_inv[w >> 24];
        asin_ += w0 * fabsf(s.x - g1.x) + w1 * fabsf(s.y - g1.y)
               + w2 * fabsf(s.z - g1.z) + w3 * fabsf(s.w - g1.w);
        acos_ += w0 * fabsf(c.x - g2.x) + w1 * fabsf(c.y - g2.y)
               + w2 * fabsf(c.z - g2.z) + w3 * fabsf(c.w - g2.w);
    }

    // block reduce
    for (int off = 16; off > 0; off >>= 1) {
        asin_ += __shfl_down_sync(0xFFFFFFFFu, asin_, off);
        acos_ += __shfl_down_sync(0xFFFFFFFFu, acos_, off);
    }
    __shared__ float ws[8], wc[8];
    const int lane = tid & 31, warp = tid >> 5;
    if (lane == 0) { ws[warp] = asin_; wc[warp] = acos_; }
    __syncthreads();
    if (tid == 0) {
        float vs = 0.0f, vc = 0.0f;
        #pragma unroll
        for (int i = 0; i < 8; i++) { vs += ws[i]; vc += wc[i]; }
        g_ploss[bid * 2 + 0] = vs;
        g_ploss[bid * 2 + 1] = vc;
    }

    // global ticket: last block writes the 5x16 output tuple
    __shared__ int s_last;
    if (tid == 0) {
        __threadfence();
        s_last = (atomicAdd(&g_tixl, 1) == NLBLK - 1);
    }
    __syncthreads();
    if (!s_last) return;
    __threadfence();

    for (int bb = warp; bb < NB; bb += 8) {      // warp w -> batches w, w+8
        float ss = 0.0f, cc = 0.0f;
        for (int x = lane; x < GL; x += 32) {
            ss += g_ploss[(bb * GL + x) * 2 + 0];
            cc += g_ploss[(bb * GL + x) * 2 + 1];
        }
        for (int off = 16; off > 0; off >>= 1) {
            ss += __shfl_down_sync(0xFFFFFFFFu, ss, off);
            cc += __shfl_down_sync(0xFFFFFFFFu, cc, off);
        }
        if (lane == 0) {
            float t = ss + cc;
            out[0 * NB + bb] = t;      // loss
            out[1 * NB + bb] = t;      // loss_direction_total
            out[2 * NB + bb] = 0.0f;   // loss_centers
            out[3 * NB + bb] = ss;     // loss_sin
            out[4 * NB + bb] = cc;     // loss_cos
        }
    }
    if (tid == 0) g_tixl = 0;          // self-reset for next graph replay
}

extern "C" void kernel_launch(void* const* d_in, const int* in_sizes, int n_in,
                              void* d_out, int out_size) {
    const float* pred = (const float*)d_in[0];   // (16,2,768,768) f32
    const int*   inst = (const int*)d_in[1];     // (16,768,768) i32
    // d_in[2] = labels (unused: W_FG == W_BG == 1)
    const float* gt   = (const float*)d_in[3];   // (16,5,768,768) f32
    float* out = (float*)d_out;                  // 80 f32

    k_hist<<<dim3(GH, NB), 256>>>(inst);
    k_loss<<<dim3(GL, NB), 256>>>(pred, gt, out);
}

// round 5
// speedup vs baseline: 1.3387x; 1.2905x over previous
#include <cuda_runtime.h>

#define NB 16
#define G 37                      // blocks per batch (37*16 = 592 = 148 SMs * 4)
#define NBLK (G * NB)
#define HWPIX (768*768)
#define NUM_IDS 128
#define NVEC (HWPIX/4)            // 147456

// ---- scratch (allocation-free __device__ globals). Everything is a plain
// store fully overwritten each run except g_tix, reset by its consumer. ----
__device__ unsigned char g_pack[(size_t)NB * HWPIX];  // ids packed to bytes
__device__ int   g_part [NBLK * NUM_IDS];             // per-block partial hists
__device__ int   g_cnt  [NB * NUM_IDS];               // per-batch counts
__device__ int   g_ni   [NB];                         // per-batch #instances
__device__ int   g_nbg  [NB];                         // per-batch bg pixels
__device__ float g_ploss[NBLK * 2];                   // per-block (sin,cos)
__device__ int   g_tix;                               // loss ticket (self-reset)

// ---------------------------------------------------------------------------
// K1: histogram partials + id byte-packing. No atomics to global, no tail.
// ---------------------------------------------------------------------------
__global__ void __launch_bounds__(256, 4) k_hist(const int* __restrict__ inst) {
    const int tid = threadIdx.x;
    const int b   = blockIdx.y;
    const int bx  = blockIdx.x;

    __shared__ int sh[NUM_IDS];
    if (tid < NUM_IDS) sh[tid] = 0;
    __syncthreads();

    const int4* pi = (const int4*)(inst + (size_t)b * HWPIX);
    uchar4*     pk = (uchar4*)(g_pack + (size_t)b * HWPIX);
    for (int i = bx * 256 + tid; i < NVEC; i += G * 256) {
        int4 v = __ldcs(pi + i);
        pk[i] = make_uchar4((unsigned char)v.x, (unsigned char)v.y,
                            (unsigned char)v.z, (unsigned char)v.w);
        atomicAdd(&sh[v.x], 1);
        atomicAdd(&sh[v.y], 1);
        atomicAdd(&sh[v.z], 1);
        atomicAdd(&sh[v.w], 1);
    }
    __syncthreads();
    if (tid < NUM_IDS)
        g_part[(b * G + bx) * NUM_IDS + tid] = sh[tid];
}

// ---------------------------------------------------------------------------
// K2: tiny parallel reduce of partials. 16 blocks x 128 threads.
// Thread tid owns id=tid for batch b: sums G partials with full MLP.
// ---------------------------------------------------------------------------
__global__ void __launch_bounds__(128) k_norm() {
    const int b  = blockIdx.x;
    const int id = threadIdx.x;

    int tot = 0;
    #pragma unroll
    for (int x = 0; x < G; x++)
        tot += g_part[(b * G + x) * NUM_IDS + id];
    g_cnt[b * NUM_IDS + id] = tot;

    // reduce ni (ids > 0 present) across the block; id 0 total = nbg
    int myni = (id > 0 && tot > 0) ? 1 : 0;
    __shared__ int s_red[128];
    __shared__ int s_bg;
    if (id == 0) s_bg = tot;
    s_red[id] = myni;
    __syncthreads();
    for (int s = 64; s > 0; s >>= 1) {
        if (id < s) s_red[id] += s_red[id + s];
        __syncthreads();
    }
    if (id == 0) { g_ni[b] = s_red[0]; g_nbg[b] = s_bg; }
}

// ---------------------------------------------------------------------------
// K3: weighted-L1 stream (byte ids, streaming loads). One balanced wave.
// ---------------------------------------------------------------------------
__global__ void __launch_bounds__(256, 4) k_loss(const float* __restrict__ pred,
                                                 const float* __restrict__ gt,
                                                 float*       __restrict__ out) {
    const int tid = threadIdx.x;
    const int b   = blockIdx.y;
    const int bx  = blockIdx.x;
    const int bid = b * G + bx;

    __shared__ float s_inv[NUM_IDS];
    {
        int ni = 0, nbg = 0;
        #pragma unroll
        for (int i = 0; i < NB; i++) { ni += g_ni[i]; nbg += g_nbg[i]; }
        float inv_bg = 1.0f / (2.0f * (float)nbg);
        float two_ni = 2.0f * (float)ni;
        if (tid < NUM_IDS) {
            float c = (float)max(g_cnt[b * NUM_IDS + tid], 1);
            s_inv[tid] = (tid == 0) ? inv_bg : 1.0f / (c * two_ni);
        }
    }
    __syncthreads();

    const float4*   ps  = (const float4*)(pred + (size_t)b * 2 * HWPIX);
    const float4*   pc  = (const float4*)(pred + (size_t)b * 2 * HWPIX + HWPIX);
    const float4*   gs  = (const float4*)(gt + (size_t)b * 5 * HWPIX + 2 * (size_t)HWPIX);
    const float4*   gc  = (const float4*)(gt + (size_t)b * 5 * HWPIX + 3 * (size_t)HWPIX);
    const unsigned* pid = (const unsigned*)(g_pack + (size_t)b * HWPIX);

    float asin_ = 0.0f, acos_ = 0.0f;
    #pragma unroll 2
    for (int i = bx * 256 + tid; i < NVEC; i += G * 256) {
        unsigned w  = __ldcs(pid + i);
        float4   s  = __ldcs(ps + i);
        float4   c  = __ldcs(pc + i);
        float4   g1 = __ldcs(gs + i);
        float4   g2 = __ldcs(gc + i);
        float w0 = s_inv[w & 0xFF];
        float w1 = s_inv[(w >> 8)  & 0xFF];
        float w2 = s_inv[(w >> 16) & 0xFF];
        float w3 = s_inv[w >> 24];
        asin_ += w0 * fabsf(s.x - g1.x) + w1 * fabsf(s.y - g1.y)
               + w2 * fabsf(s.z - g1.z) + w3 * fabsf(s.w - g1.w);
        acos_ += w0 * fabsf(c.x - g2.x) + w1 * fabsf(c.y - g2.y)
               + w2 * fabsf(c.z - g2.z) + w3 * fabsf(c.w - g2.w);
    }

    // block reduce
    for (int off = 16; off > 0; off >>= 1) {
        asin_ += __shfl_down_sync(0xFFFFFFFFu, asin_, off);
        acos_ += __shfl_down_sync(0xFFFFFFFFu, acos_, off);
    }
    __shared__ float ws[8], wc[8];
    const int lane = tid & 31, warp = tid >> 5;
    if (lane == 0) { ws[warp] = asin_; wc[warp] = acos_; }
    __syncthreads();
    if (tid == 0) {
        float vs = 0.0f, vc = 0.0f;
        #pragma unroll
        for (int i = 0; i < 8; i++) { vs += ws[i]; vc += wc[i]; }
        g_ploss[bid * 2 + 0] = vs;
        g_ploss[bid * 2 + 1] = vc;
    }

    // global ticket: last block writes the 5x16 output tuple
    __shared__ int s_last;
    if (tid == 0) {
        __threadfence();
        s_last = (atomicAdd(&g_tix, 1) == NBLK - 1);
    }
    __syncthreads();
    if (!s_last) return;
    __threadfence();

    for (int bb = warp; bb < NB; bb += 8) {      // warp w -> batches w, w+8
        float ss = 0.0f, cc = 0.0f;
        for (int x = lane; x < G; x += 32) {
            ss += g_ploss[(bb * G + x) * 2 + 0];
            cc += g_ploss[(bb * G + x) * 2 + 1];
        }
        for (int off = 16; off > 0; off >>= 1) {
            ss += __shfl_down_sync(0xFFFFFFFFu, ss, off);
            cc += __shfl_down_sync(0xFFFFFFFFu, cc, off);
        }
        if (lane == 0) {
            float t = ss + cc;
            out[0 * NB + bb] = t;      // loss
            out[1 * NB + bb] = t;      // loss_direction_total
            out[2 * NB + bb] = 0.0f;   // loss_centers
            out[3 * NB + bb] = ss;     // loss_sin
            out[4 * NB + bb] = cc;     // loss_cos
        }
    }
    if (tid == 0) g_tix = 0;           // self-reset for next graph replay
}

extern "C" void kernel_launch(void* const* d_in, const int* in_sizes, int n_in,
                              void* d_out, int out_size) {
    const float* pred = (const float*)d_in[0];   // (16,2,768,768) f32
    const int*   inst = (const int*)d_in[1];     // (16,768,768) i32
    // d_in[2] = labels (unused: W_FG == W_BG == 1)
    const float* gt   = (const float*)d_in[3];   // (16,5,768,768) f32
    float* out = (float*)d_out;                  // 80 f32

    k_hist<<<dim3(G, NB), 256>>>(inst);
    k_norm<<<NB, 128>>>();
    k_loss<<<dim3(G, NB), 256>>>(pred, gt, out);
}